// round 8
// baseline (speedup 1.0000x reference)
#include <cuda_runtime.h>
#include <math.h>

#define DIM 4096

// First 30 primes (== P_DIAG for DIM=4096).
__constant__ int c_primes[30] = {
    2, 3, 5, 7, 11, 13, 17, 19, 23, 29,
    31, 37, 41, 43, 47, 53, 59, 61, 67, 71,
    73, 79, 83, 89, 97, 101, 103, 107, 109, 113};

// ---------------------------------------------------------------------------
// Single kernel, zero synchronization.
//
// Math reduction of the reference:
//  * Off-diagonal prime terms are purely imaginary and cancel EXACTLY under
//    the Hermitization 0.5*(H + H^dagger); output (= Re(H) as float32) is
//    a pure diagonal: d[n] = Re(exp(-s ln n)) + theta*ln(p)*corr*zeta2/p.
//  * reg = max(1e-22, ||H||_F * 1e-18) ~ 3.6e-18 is ADDITIVELY INVISIBLE in
//    float32 (elements ~n^-0.5): it cannot flip any stored fp32 bit unless
//    the element is < ~1e-11, and its norm-level contribution is ~1e-18.
//    So the Frobenius reduction and all cross-block sync are dropped.
//
// Geometry: 4096 blocks x 256 threads x 4 float4-stores = 64 MiB exactly.
// Per iteration k, a warp writes 512 contiguous bytes (coalesced STG.128).
// The 4096 threads whose float4 lands on the diagonal compute their own
// element inline in fp64 — latency fully hidden under the streaming fill.
// ---------------------------------------------------------------------------
__global__ __launch_bounds__(256)
void fill_kernel(const float* sr_p, const float* si_p, const float* th_p,
                 float4* __restrict__ out) {
    const unsigned int base = blockIdx.x * 1024u + threadIdx.x;

#pragma unroll
    for (int k = 0; k < 4; k++) {
        const unsigned int idx = base + (unsigned int)k * 256u;  // float4 slot
        const unsigned int row = idx >> 10;      // 1024 float4 per matrix row
        const unsigned int col4 = idx & 1023u;

        float4 v = make_float4(0.f, 0.f, 0.f, 0.f);

        if (col4 == (row >> 2)) {
            // This float4 contains diagonal element (row, row): compute it.
            const double ZETA2 = 1.6449340668482264365;  // pi^2/6
            const double CUTOFF = 1e-80;
            const double sr = sr_p ? (double)*sr_p : 0.5;
            const double si = si_p ? (double)*si_p : 14.134725141734693;
            const double th = th_p ? (double)*th_p : 1e-22;

            const int n = (int)row + 1;              // 1..4096
            const double logn = log((double)n);
            const bool in_range = (fabs(sr) < 30.0) && (fabs(si) < 500.0);
            const bool safe = (-sr * logn) > -80.0;
            // Re(exp(-s ln n)) = exp(-sr ln n) * cos(si ln n)
            double d = (in_range || safe) ? exp(-sr * logn) * cos(si * logn)
                                          : CUTOFF;
            if (n <= 113) {
                bool isp = false;
#pragma unroll
                for (int j = 0; j < 30; j++) isp = isp || (n == c_primes[j]);
                if (isp) {
                    const double corr = fmin(sqrt(sr * sr + si * si), 5.0);
                    d += th * logn * corr * (ZETA2 / (double)n);
                }
            }

            const float df = (float)d;
            switch (row & 3u) {
                case 0:  v.x = df; break;
                case 1:  v.y = df; break;
                case 2:  v.z = df; break;
                default: v.w = df; break;
            }
        }

        out[idx] = v;
    }
}

extern "C" void kernel_launch(void* const* d_in, const int* in_sizes, int n_in,
                              void* d_out, int out_size) {
    (void)in_sizes; (void)out_size;
    const float* sr = (n_in >= 1) ? (const float*)d_in[0] : 0;
    const float* si = (n_in >= 2) ? (const float*)d_in[1] : 0;
    const float* th = (n_in >= 3) ? (const float*)d_in[2] : 0;

    // 4096 blocks * 256 threads * 4 * 16 B = 67,108,864 B = out_size * 4.
    fill_kernel<<<4096, 256>>>(sr, si, th, (float4*)d_out);
}

// round 9
// speedup vs baseline: 1.6061x; 1.6061x over previous
#include <cuda_runtime.h>
#include <math.h>

#define DIM 4096
#define FILL_BLOCKS 16384   // 16384 * 256 threads * 16 B = 64 MiB exactly
#define DIAG_BLOCKS 32      // 32 * 128 threads = 4096 diagonal elements

// First 30 primes (== P_DIAG for DIM=4096).
__constant__ int c_primes[30] = {
    2, 3, 5, 7, 11, 13, 17, 19, 23, 29,
    31, 37, 41, 43, 47, 53, 59, 61, 67, 71,
    73, 79, 83, 89, 97, 101, 103, 107, 109, 113};

// ---------------------------------------------------------------------------
// ONE kernel, ZERO synchronization, disjoint writes:
//  * Blocks [0, 16384): R6's empirically-fastest fill shape (1 float4 per
//    thread), except the store is predicated OFF for the 4096 float4 slots
//    that contain a diagonal element.
//  * Blocks [16384, 16416): compute the fp64 diagonal (one element per
//    thread) and write exactly those 4096 slots. Address sets are disjoint,
//    so no ordering is required; the ~3 us fp64 tail hides under the fill.
//
// Math reduction (validated R5-R8, rel_err 1.8e-6):
//  * Off-diagonal prime terms are purely imaginary -> cancel EXACTLY under
//    0.5*(H + H^dagger); Re(H) is diagonal.
//  * reg = max(1e-22, ||H||_F*1e-18) ~ 3.6e-18 is additively invisible in
//    float32 output -> Frobenius reduction dropped entirely.
// ---------------------------------------------------------------------------
__global__ __launch_bounds__(256)
void build_kernel(const float* sr_p, const float* si_p, const float* th_p,
                  float4* __restrict__ out) {
    const unsigned int bid = blockIdx.x;

    if (bid < FILL_BLOCKS) {
        // -------- streaming zero fill (skip diagonal slots) --------
        const unsigned int idx = bid * 256u + threadIdx.x;  // float4 slot
        const unsigned int row = idx >> 10;     // 1024 float4 per matrix row
        const unsigned int col4 = idx & 1023u;
        if (col4 != (row >> 2)) {
            out[idx] = make_float4(0.f, 0.f, 0.f, 0.f);
        }
        return;
    }

    // -------- diagonal writer blocks --------
    if (threadIdx.x >= 128) return;
    const unsigned int t = (bid - FILL_BLOCKS) * 128u + threadIdx.x;  // 0..4095
    const int n = (int)t + 1;                                         // 1..4096

    const double ZETA2 = 1.6449340668482264365;  // pi^2/6
    const double CUTOFF = 1e-80;
    const double sr = sr_p ? (double)*sr_p : 0.5;
    const double si = si_p ? (double)*si_p : 14.134725141734693;
    const double th = th_p ? (double)*th_p : 1e-22;

    const double logn = log((double)n);
    const bool in_range = (fabs(sr) < 30.0) && (fabs(si) < 500.0);
    const bool safe = (-sr * logn) > -80.0;
    // Re(exp(-s ln n)) = exp(-sr ln n) * cos(si ln n)
    double d = (in_range || safe) ? exp(-sr * logn) * cos(si * logn)
                                  : CUTOFF;
    if (n <= 113) {
        bool isp = false;
#pragma unroll
        for (int j = 0; j < 30; j++) isp = isp || (n == c_primes[j]);
        if (isp) {
            const double corr = fmin(sqrt(sr * sr + si * si), 5.0);
            d += th * logn * corr * (ZETA2 / (double)n);
        }
    }

    // Write the diagonal-containing float4 slot (disjoint from fill writes).
    float4 v = make_float4(0.f, 0.f, 0.f, 0.f);
    const float df = (float)d;
    switch (t & 3u) {
        case 0:  v.x = df; break;
        case 1:  v.y = df; break;
        case 2:  v.z = df; break;
        default: v.w = df; break;
    }
    out[(size_t)t * 1024u + (t >> 2)] = v;
}

extern "C" void kernel_launch(void* const* d_in, const int* in_sizes, int n_in,
                              void* d_out, int out_size) {
    (void)in_sizes; (void)out_size;
    const float* sr = (n_in >= 1) ? (const float*)d_in[0] : 0;
    const float* si = (n_in >= 2) ? (const float*)d_in[1] : 0;
    const float* th = (n_in >= 3) ? (const float*)d_in[2] : 0;

    build_kernel<<<FILL_BLOCKS + DIAG_BLOCKS, 256>>>(sr, si, th,
                                                     (float4*)d_out);
}

// round 10
// speedup vs baseline: 1.8004x; 1.1210x over previous
#include <cuda_runtime.h>
#include <math.h>

#define DIM 4096
#define DIAG_BLOCKS 32      // 32 * 128 threads = 4096 diagonal elements
#define FILL_BLOCKS 16384   // 16384 * 256 threads * 16 B = 64 MiB exactly

// First 30 primes (== P_DIAG for DIM=4096).
__constant__ int c_primes[30] = {
    2, 3, 5, 7, 11, 13, 17, 19, 23, 29,
    31, 37, 41, 43, 47, 53, 59, 61, 67, 71,
    73, 79, 83, 89, 97, 101, 103, 107, 109, 113};

// ---------------------------------------------------------------------------
// ONE kernel, ZERO synchronization, disjoint writes.
//  * Blocks [0, 32): fp64 diagonal, one element/thread. FIRST in the grid so
//    they start in wave 1 and their ~3 us of transcendentals hide under the
//    fill instead of trailing it (R9's measured 4 us tail).
//  * Blocks [32, 16416): R6's empirically-fastest fill shape (1 float4 per
//    thread), store predicated OFF for the 4096 diagonal-containing slots.
// Address sets are disjoint -> no ordering, no flags, no atomics.
//
// Math reduction (validated R5-R9, rel_err 1.802e-6):
//  * Off-diagonal prime terms are purely imaginary -> cancel EXACTLY under
//    0.5*(H + H^dagger); Re(H) is diagonal.
//  * reg = max(1e-22, ||H||_F*1e-18) ~ 3.6e-18 is additively invisible in
//    float32 output -> Frobenius reduction dropped entirely.
// ---------------------------------------------------------------------------
__global__ __launch_bounds__(256)
void build_kernel(const float* sr_p, const float* si_p, const float* th_p,
                  float4* __restrict__ out) {
    const unsigned int bid = blockIdx.x;

    if (bid >= DIAG_BLOCKS) {
        // -------- streaming zero fill (skip diagonal slots) --------
        const unsigned int idx = (bid - DIAG_BLOCKS) * 256u + threadIdx.x;
        const unsigned int row = idx >> 10;     // 1024 float4 per matrix row
        const unsigned int col4 = idx & 1023u;
        if (col4 != (row >> 2)) {
            out[idx] = make_float4(0.f, 0.f, 0.f, 0.f);
        }
        return;
    }

    // -------- diagonal writer blocks (wave-1 resident) --------
    if (threadIdx.x >= 128) return;
    const unsigned int t = bid * 128u + threadIdx.x;   // 0..4095
    const int n = (int)t + 1;                          // 1..4096

    const double ZETA2 = 1.6449340668482264365;  // pi^2/6
    const double CUTOFF = 1e-80;
    const double sr = sr_p ? (double)*sr_p : 0.5;
    const double si = si_p ? (double)*si_p : 14.134725141734693;
    const double th = th_p ? (double)*th_p : 1e-22;

    const double logn = log((double)n);
    const bool in_range = (fabs(sr) < 30.0) && (fabs(si) < 500.0);
    const bool safe = (-sr * logn) > -80.0;
    // Re(exp(-s ln n)) = exp(-sr ln n) * cos(si ln n)
    double d = (in_range || safe) ? exp(-sr * logn) * cos(si * logn)
                                  : CUTOFF;
    if (n <= 113) {
        bool isp = false;
#pragma unroll
        for (int j = 0; j < 30; j++) isp = isp || (n == c_primes[j]);
        if (isp) {
            const double corr = fmin(sqrt(sr * sr + si * si), 5.0);
            d += th * logn * corr * (ZETA2 / (double)n);
        }
    }

    // Write the diagonal-containing float4 slot (disjoint from fill writes).
    float4 v = make_float4(0.f, 0.f, 0.f, 0.f);
    const float df = (float)d;
    switch (t & 3u) {
        case 0:  v.x = df; break;
        case 1:  v.y = df; break;
        case 2:  v.z = df; break;
        default: v.w = df; break;
    }
    out[(size_t)t * 1024u + (t >> 2)] = v;
}

extern "C" void kernel_launch(void* const* d_in, const int* in_sizes, int n_in,
                              void* d_out, int out_size) {
    (void)in_sizes; (void)out_size;
    const float* sr = (n_in >= 1) ? (const float*)d_in[0] : 0;
    const float* si = (n_in >= 2) ? (const float*)d_in[1] : 0;
    const float* th = (n_in >= 3) ? (const float*)d_in[2] : 0;

    build_kernel<<<DIAG_BLOCKS + FILL_BLOCKS, 256>>>(sr, si, th,
                                                     (float4*)d_out);
}